// round 14
// baseline (speedup 1.0000x reference)
#include <cuda_runtime.h>
#include <math.h>

#define N   384
#define NN  (384*384)
#define JQ  96

// ---- scratch (device globals; no allocation allowed) ----
__device__ float g_Mk  [512*128];     // rs * Wk_edge^T @ Wq   [e*8+h][c]
__device__ float g_WveT[64*256];      // Wv_edge transposed    [e][hv]
__device__ float g_Qk  [384*512];     // [i][e*8+h]
__device__ float g_VnT [384*256];     // [i][hv]
__device__ float g_nfT [384*256];     // [i][hv]
__device__ float g_hEo [64*N];
__device__ float g_mask[N];
__device__ float g_part[384*4*528];   // per (i, quarter): m[8], s[8], T[8][64]
__device__ int   g_ctr [384];

// ---- packed f32x2 helpers (Blackwell FFMA2) ----
__device__ __forceinline__ unsigned long long pk2(float a, float b) {
    unsigned long long d;
    asm("mov.b64 %0, {%1, %2};" : "=l"(d) : "f"(a), "f"(b));
    return d;
}
__device__ __forceinline__ unsigned long long fma2(unsigned long long a,
                                                   unsigned long long b,
                                                   unsigned long long c) {
    unsigned long long d;
    asm("fma.rn.f32x2 %0, %1, %2, %3;" : "=l"(d) : "l"(a), "l"(b), "l"(c));
    return d;
}
__device__ __forceinline__ float2 upk(unsigned long long v) {
    float2 r;
    asm("mov.b64 {%0, %1}, %2;" : "=f"(r.x), "=f"(r.y) : "l"(v));
    return r;
}
union F4U { float4 f; unsigned long long u[2]; };

// ---- cp.async helpers ----
__device__ __forceinline__ void cp16(void* dst, const void* src) {
    unsigned d = (unsigned)__cvta_generic_to_shared(dst);
    asm volatile("cp.async.cg.shared.global [%0], [%1], 16;" :: "r"(d), "l"(src));
}
#define CP_COMMIT() asm volatile("cp.async.commit_group;" ::: "memory")
#define CP_WAIT(n)  asm volatile("cp.async.wait_group %0;" :: "n"(n) : "memory")

// ============================================================
// Kernel 1: weights prep. Blocks 0..15: Mk = rs*Wk_edge^T@Wq.
// Block 16: WveT fill. Block 0 also decodes mask + resets g_ctr.
// grid(17), 256 thr.
// ============================================================
__global__ __launch_bounds__(256) void k_mk(
    const float* __restrict__ Wq,
    const float* __restrict__ Wk,
    const float* __restrict__ Wv,
    const unsigned int* __restrict__ maskw)
{
    __shared__ int s_flagF, s_flagB;
    int tid = threadIdx.x;
    const float rs = 0.17677669529663687f;

    if (blockIdx.x == 16) {
        #pragma unroll
        for (int k = 0; k < 64; k++) {
            int idx = k * 256 + tid;
            int e = idx >> 8, hv = idx & 255;
            g_WveT[idx] = Wv[hv * 192 + 128 + e];
        }
        return;
    }

    if (blockIdx.x == 0) {
        if (tid == 0) { s_flagF = 0; s_flagB = 0; }
        __syncthreads();
        if (tid < 96) {
            unsigned v = maskw[tid];
            if (v == 0x3f800000u) atomicOr(&s_flagF, 1);   // float32 1.0
            else if (v > 1u)      atomicOr(&s_flagB, 1);   // packed u8
        }
        __syncthreads();
        bool byte_mode = (!s_flagF) && s_flagB;
        for (int j = tid; j < N; j += 256) {
            float val;
            if (byte_mode) {
                unsigned w = maskw[j >> 2];
                val = ((w >> ((j & 3) * 8)) & 0xffu) ? 1.0f : 0.0f;
            } else {
                val = maskw[j] ? 1.0f : 0.0f;   // int32 or f32 bits
            }
            g_mask[j] = val;
            g_ctr[j] = 0;
        }
    }

    int r = blockIdx.x * 32 + (tid >> 3);
    int c0 = (tid & 7) * 16;
    int e = r >> 3, h = r & 7;
    float acc[16];
    #pragma unroll
    for (int u = 0; u < 16; u++) acc[u] = 0.f;
    #pragma unroll 4
    for (int a = 0; a < 32; a++) {
        float w = Wk[(h * 32 + a) * 192 + 128 + e];
        const float* wq = Wq + (h * 32 + a) * 128 + c0;
        #pragma unroll
        for (int u = 0; u < 16; u += 4) {
            float4 q = *(const float4*)(wq + u);
            acc[u+0] = fmaf(w, q.x, acc[u+0]);
            acc[u+1] = fmaf(w, q.y, acc[u+1]);
            acc[u+2] = fmaf(w, q.z, acc[u+2]);
            acc[u+3] = fmaf(w, q.w, acc[u+3]);
        }
    }
    #pragma unroll
    for (int u = 0; u < 16; u++) g_Mk[r * 128 + c0 + u] = rs * acc[u];
}

// ============================================================
// Kernel 2: fused GEMM [768 rows x 128k x 384 cols]:
// rows 0..511 -> g_Qk [i][r]; rows 512..767 -> g_VnT [i][hv].
// Both written COALESCED via smem-tile transpose.
// grid(24,12), 256 thr, tile 32x32.
// ============================================================
__global__ __launch_bounds__(256) void k_prep(
    const float* __restrict__ nodes,
    const float* __restrict__ Wv)
{
    __shared__ float Ws[32][33];
    __shared__ float Ns[32][36];
    int tid = threadIdx.x;
    int r0 = blockIdx.x * 32, n0 = blockIdx.y * 32;
    int co = tid & 31, ro = (tid >> 5) * 4;
    float acc[4] = {0.f, 0.f, 0.f, 0.f};

    for (int k0 = 0; k0 < 128; k0 += 32) {
        {
            int rr = tid >> 3, kl = (tid & 7) * 4;
            int r = r0 + rr;
            const float* wp = (r < 512) ? (g_Mk + r * 128) : (Wv + (r - 512) * 192);
            float4 w = *(const float4*)(wp + k0 + kl);
            Ws[rr][kl+0] = w.x; Ws[rr][kl+1] = w.y;
            Ws[rr][kl+2] = w.z; Ws[rr][kl+3] = w.w;
        }
        {
            int kk = tid >> 3, cl = (tid & 7) * 4;
            float4 v = *(const float4*)(nodes + (k0 + kk) * N + n0 + cl);
            Ns[kk][cl+0] = v.x; Ns[kk][cl+1] = v.y;
            Ns[kk][cl+2] = v.z; Ns[kk][cl+3] = v.w;
        }
        __syncthreads();
        #pragma unroll
        for (int k = 0; k < 32; k++) {
            float ev = Ns[k][co];
            acc[0] = fmaf(Ws[ro+0][k], ev, acc[0]);
            acc[1] = fmaf(Ws[ro+1][k], ev, acc[1]);
            acc[2] = fmaf(Ws[ro+2][k], ev, acc[2]);
            acc[3] = fmaf(Ws[ro+3][k], ev, acc[3]);
        }
        __syncthreads();
    }

    // stage to smem (reuse Ns) then write transposed, coalesced
    #pragma unroll
    for (int q = 0; q < 4; q++) Ns[ro + q][co] = acc[q];
    __syncthreads();

    int i_loc = tid >> 3, rl = (tid & 7) * 4;
    float4 o = make_float4(Ns[rl][i_loc], Ns[rl+1][i_loc],
                           Ns[rl+2][i_loc], Ns[rl+3][i_loc]);
    if (r0 < 512)
        *(float4*)(g_Qk  + (size_t)(n0 + i_loc) * 512 + r0 + rl) = o;
    else
        *(float4*)(g_VnT + (size_t)(n0 + i_loc) * 256 + (r0 - 512) + rl) = o;
}

// ============================================================
// Kernel 3: attention partials + fused last-CTA combine.
// grid(1536) = 384 i x 4 quarters, 256 thr, ~35KB static smem.
// cp.async split staging; last CTA per row combines -> g_nfT.
// ============================================================
#define ES_ST 100
#define PH_ST 100
#define P2W   196

__global__ __launch_bounds__(256) void k_attnA(const float* __restrict__ edges)
{
    __shared__ float Es[64 * ES_ST];
    __shared__ float s_ph[8 * PH_ST];
    __shared__ float p2f[4 * P2W];
    __shared__ float s_Qk[512];
    __shared__ float s_mf[JQ];
    __shared__ float s_ms[16];
    __shared__ float s_fac[32];
    __shared__ int   s_win;

    int bx = blockIdx.x;
    int i = bx >> 2, qn = bx & 3, jb = qn * JQ;
    int tid = threadIdx.x, lane = tid & 31, wid = tid >> 5;

    // cp.async staging, two 32-e chunks. 64 x 24 float4 = 1536; 6/thread.
    const float* erow = edges + (size_t)i * N + jb;
    #pragma unroll
    for (int it = 0; it < 3; it++) {
        int idx = it * 256 + tid;
        int e = idx / 24, c4 = idx - e * 24;
        cp16(&Es[e * ES_ST + c4 * 4], erow + (size_t)e * NN + c4 * 4);
    }
    CP_COMMIT();
    #pragma unroll
    for (int it = 3; it < 6; it++) {
        int idx = it * 256 + tid;
        int e = idx / 24, c4 = idx - e * 24;
        cp16(&Es[e * ES_ST + c4 * 4], erow + (size_t)e * NN + c4 * 4);
    }
    CP_COMMIT();

    s_Qk[tid]       = g_Qk[(size_t)i * 512 + tid];
    s_Qk[256 + tid] = g_Qk[(size_t)i * 512 + 256 + tid];
    if (tid < JQ) s_mf[tid] = g_mask[jb + tid];

    // pass 1: sim. thread = (jg of 48, hh of 2). 96 active threads.
    unsigned long long acc2[4] = {0ull, 0ull, 0ull, 0ull};
    int jg = tid >> 1, hh = tid & 1, j0 = jg * 2;
    const float* ep = Es + j0;
    const float* qp = s_Qk + hh * 4;

    CP_WAIT(1);
    __syncthreads();
    if (tid < 2 * 48) {
        #pragma unroll 8
        for (int e = 0; e < 32; e++) {
            float2 ev = *(const float2*)(ep + e * ES_ST);
            unsigned long long ed0 = pk2(ev.x, ev.x);
            unsigned long long ed1 = pk2(ev.y, ev.y);
            F4U q; q.f = *(const float4*)(qp + e * 8);
            acc2[0] = fma2(q.u[0], ed0, acc2[0]);
            acc2[1] = fma2(q.u[1], ed0, acc2[1]);
            acc2[2] = fma2(q.u[0], ed1, acc2[2]);
            acc2[3] = fma2(q.u[1], ed1, acc2[3]);
        }
    }
    CP_WAIT(0);
    __syncthreads();
    if (tid < 2 * 48) {
        #pragma unroll 8
        for (int e = 32; e < 64; e++) {
            float2 ev = *(const float2*)(ep + e * ES_ST);
            unsigned long long ed0 = pk2(ev.x, ev.x);
            unsigned long long ed1 = pk2(ev.y, ev.y);
            F4U q; q.f = *(const float4*)(qp + e * 8);
            acc2[0] = fma2(q.u[0], ed0, acc2[0]);
            acc2[1] = fma2(q.u[1], ed0, acc2[1]);
            acc2[2] = fma2(q.u[0], ed1, acc2[2]);
            acc2[3] = fma2(q.u[1], ed1, acc2[3]);
        }
        float m0 = (s_mf[j0]     > 0.f) ? 0.f : 1.f;
        float m1 = (s_mf[j0 + 1] > 0.f) ? 0.f : 1.f;
        float2 a0 = upk(acc2[0]), a1 = upk(acc2[1]);
        float2 b0 = upk(acc2[2]), b1 = upk(acc2[3]);
        int hb = hh * 4;
        s_ph[(hb+0)*PH_ST + j0] = m0 ? -INFINITY : a0.x;
        s_ph[(hb+1)*PH_ST + j0] = m0 ? -INFINITY : a0.y;
        s_ph[(hb+2)*PH_ST + j0] = m0 ? -INFINITY : a1.x;
        s_ph[(hb+3)*PH_ST + j0] = m0 ? -INFINITY : a1.y;
        s_ph[(hb+0)*PH_ST + j0+1] = m1 ? -INFINITY : b0.x;
        s_ph[(hb+1)*PH_ST + j0+1] = m1 ? -INFINITY : b0.y;
        s_ph[(hb+2)*PH_ST + j0+1] = m1 ? -INFINITY : b1.x;
        s_ph[(hb+3)*PH_ST + j0+1] = m1 ? -INFINITY : b1.y;
    }
    __syncthreads();

    // local softmax stats: warp h owns row h
    {
        int h = wid;
        float* row = s_ph + h * PH_ST;
        float m = -INFINITY;
        #pragma unroll
        for (int jl = lane; jl < JQ; jl += 32) m = fmaxf(m, row[jl]);
        #pragma unroll
        for (int o = 16; o; o >>= 1) m = fmaxf(m, __shfl_xor_sync(0xffffffffu, m, o));
        float mexp = (m == -INFINITY) ? 0.f : m;
        float sum = 0.f;
        #pragma unroll
        for (int jl = lane; jl < JQ; jl += 32) {
            float ev = __expf(row[jl] - mexp);
            row[jl] = ev;
            sum += ev;
        }
        #pragma unroll
        for (int o = 16; o; o >>= 1) sum += __shfl_xor_sync(0xffffffffu, sum, o);
        if (lane == 0) { s_ms[h] = m; s_ms[8 + h] = sum; }
    }
    __syncthreads();

    // repack raw exp into h-pair float2 rows (384 items)
    #pragma unroll
    for (int k = 0; k < 2; k++) {
        int idx = k * 256 + tid;
        if (idx < 4 * JQ) {
            int hp = idx / JQ, j = idx - hp * JQ;
            float x = s_ph[(2*hp)   * PH_ST + j];
            float y = s_ph[(2*hp+1) * PH_ST + j];
            *(float2*)&p2f[hp * P2W + 2*j] = make_float2(x, y);
        }
    }
    __syncthreads();

    // pass 2: T[2hp..2hp+1][e] owned entirely by thread (e, hp)
    float* gp = g_part + ((size_t)i * 4 + qn) * 528;
    {
        int e = tid >> 2, hp = tid & 3;
        const float* epp = Es + e * ES_ST;
        const float* pp = p2f + hp * P2W;
        unsigned long long t2[4] = {0ull, 0ull, 0ull, 0ull};
        #pragma unroll 6
        for (int j = 0; j < JQ; j += 4) {
            float4 ev4 = *(const float4*)(epp + j);
            F4U pA; pA.f = *(const float4*)(pp + 2*j);
            F4U pB; pB.f = *(const float4*)(pp + 2*j + 4);
            t2[0] = fma2(pA.u[0], pk2(ev4.x, ev4.x), t2[0]);
            t2[1] = fma2(pA.u[1], pk2(ev4.y, ev4.y), t2[1]);
            t2[2] = fma2(pB.u[0], pk2(ev4.z, ev4.z), t2[2]);
            t2[3] = fma2(pB.u[1], pk2(ev4.w, ev4.w), t2[3]);
        }
        float2 t0 = upk(t2[0]), t1 = upk(t2[1]);
        float2 t3 = upk(t2[2]), t4 = upk(t2[3]);
        gp[16 + (2*hp)   * 64 + e] = (t0.x + t1.x) + (t3.x + t4.x);
        gp[16 + (2*hp+1) * 64 + e] = (t0.y + t1.y) + (t3.y + t4.y);
    }
    if (tid < 16) gp[tid] = s_ms[tid];

    // ---- split-K: last CTA for row i combines (threadFenceReduction) ----
    __syncthreads();
    __threadfence();
    if (tid == 0) s_win = (atomicAdd(&g_ctr[i], 1) == 3) ? 1 : 0;
    __syncthreads();
    if (!s_win) return;
    __threadfence();

    float maski = g_mask[i];
    const float* gall = g_part + (size_t)i * 4 * 528;

    if (tid < 32) {
        int q = tid >> 3, h = tid & 7;
        float m = gall[q * 528 + h];
        float s = gall[q * 528 + 8 + h];
        float mg = m;
        mg = fmaxf(mg, __shfl_xor_sync(0xffffffffu, mg, 8));
        mg = fmaxf(mg, __shfl_xor_sync(0xffffffffu, mg, 16));
        float mg2 = (mg == -INFINITY) ? 0.f : mg;
        float w = s * __expf(m - mg2);
        float tot = w;
        tot += __shfl_xor_sync(0xffffffffu, tot, 8);
        tot += __shfl_xor_sync(0xffffffffu, tot, 16);
        s_fac[q * 8 + h] = __expf(m - mg2) * maski / tot;
    }
    __syncthreads();

    float* s_T = p2f;   // reuse (784 >= 512 floats)
    #pragma unroll
    for (int r = 0; r < 2; r++) {
        int idx = r * 256 + tid;
        int h = idx >> 6;
        float a = fmaf(s_fac[h],      gall[16 + idx],
                  s_fac[8 + h]  * gall[528 + 16 + idx]);
        float b = fmaf(s_fac[16 + h], gall[1056 + 16 + idx],
                  s_fac[24 + h] * gall[1584 + 16 + idx]);
        s_T[idx] = a + b;
    }
    __syncthreads();

    {
        int hv = tid, h = hv >> 5;
        const float* st = s_T + h * 64;
        float a0 = g_VnT[(size_t)i * 256 + hv] * maski;
        float a1 = 0.f;
        #pragma unroll 8
        for (int e = 0; e < 64; e += 2) {
            a0 = fmaf(g_WveT[e * 256 + hv],       st[e],     a0);
            a1 = fmaf(g_WveT[(e + 1) * 256 + hv], st[e + 1], a1);
        }
        g_nfT[(size_t)i * 256 + hv] = a0 + a1;
    }
}

// ============================================================
// Kernel 4: node_out = Wo@nf ; hEo = 0.5*We[:,:256]@nf
// Reads g_nfT [i][hv] with in-register transpose staging.
// grid(12,12), 256 thr, tile 16 rows x 32 cols.
// ============================================================
__global__ __launch_bounds__(256) void k_post(
    const float* __restrict__ Wo,
    const float* __restrict__ We,
    float* __restrict__ out)
{
    __shared__ float Ws[16][33];
    __shared__ float Ns[32][36];
    int tid = threadIdx.x;
    int r0 = blockIdx.x * 16, n0 = blockIdx.y * 32;
    int co = tid & 31, ro = (tid >> 5) * 2;
    float acc[2] = {0.f, 0.f};

    int rr = tid >> 4, kl = (tid & 15) * 2;
    int n_loc = tid >> 3, kkl = (tid & 7) * 4;
    const float* wp;
    {
        int r = r0 + rr;
        wp = (r < 128) ? (Wo + r * 256) : (We + (r - 128) * 320);
    }

    for (int k0 = 0; k0 < 256; k0 += 32) {
        {
            float2 w = *(const float2*)(wp + k0 + kl);
            Ws[rr][kl+0] = w.x; Ws[rr][kl+1] = w.y;
        }
        {
            float4 v = *(const float4*)(g_nfT + (size_t)(n0 + n_loc) * 256 + k0 + kkl);
            Ns[kkl+0][n_loc] = v.x; Ns[kkl+1][n_loc] = v.y;
            Ns[kkl+2][n_loc] = v.z; Ns[kkl+3][n_loc] = v.w;
        }
        __syncthreads();
        #pragma unroll
        for (int k = 0; k < 32; k++) {
            float ev = Ns[k][co];
            acc[0] = fmaf(Ws[ro+0][k], ev, acc[0]);
            acc[1] = fmaf(Ws[ro+1][k], ev, acc[1]);
        }
        __syncthreads();
    }
    #pragma unroll
    for (int q = 0; q < 2; q++) {
        int rq = r0 + ro + q;
        if (rq < 128) out[rq * N + n0 + co] = acc[q];
        else          g_hEo[(rq - 128) * N + n0 + co] = 0.5f * acc[q];
    }
}

// ============================================================
// Kernel 5: edge_out. grid(576), 256 thr, 2 CTAs/SM.
// CTA tile 64o x 256c, thread 8o x 8c, FFMA2 o-pairs.
// cp.async double-buffered staging (two 32-e chunks).
// ============================================================
#define EG_ST 260
#define EDGE_SMEM ((64*68 + 64*EG_ST) * 4)

__global__ __launch_bounds__(256, 2) void k_edge(
    const float* __restrict__ edges,
    const float* __restrict__ We,
    float* __restrict__ out)
{
    extern __shared__ float esm[];
    float* Ws = esm;              // [64][68]  Ws[e][o]
    float* Es = esm + 64 * 68;    // [64][260]

    int tid = threadIdx.x, lane = tid & 31, wid = tid >> 5;
    size_t cbase = (size_t)blockIdx.x * 256;

    #pragma unroll
    for (int it = 0; it < 8; it++) {
        int idx = it * 256 + tid;
        int e = idx >> 6, c4 = idx & 63;
        cp16(&Es[e * EG_ST + c4 * 4], edges + (size_t)e * NN + cbase + c4 * 4);
    }
    CP_COMMIT();
    #pragma unroll
    for (int it = 8; it < 16; it++) {
        int idx = it * 256 + tid;
        int e = idx >> 6, c4 = idx & 63;
        cp16(&Es[e * EG_ST + c4 * 4], edges + (size_t)e * NN + cbase + c4 * 4);
    }
    CP_COMMIT();

    {
        int o = tid >> 2, e0 = (tid & 3) * 16;
        const float* wp = We + o * 320 + 256 + e0;
        #pragma unroll
        for (int u = 0; u < 16; u += 4) {
            float4 w = *(const float4*)(wp + u);
            Ws[(e0+u+0)*68 + o] = w.x; Ws[(e0+u+1)*68 + o] = w.y;
            Ws[(e0+u+2)*68 + o] = w.z; Ws[(e0+u+3)*68 + o] = w.w;
        }
    }

    int o0 = wid * 8;
    int cl = lane * 4;

    unsigned long long acc2[4][8];
    #pragma unroll
    for (int op = 0; op < 4; op++)
        #pragma unroll
        for (int p = 0; p < 8; p++) acc2[op][p] = 0ull;

    CP_WAIT(1);
    __syncthreads();
    #pragma unroll 4
    for (int e = 0; e < 32; e++) {
        const float* wr = Ws + e * 68 + o0;
        F4U w0; w0.f = *(const float4*)wr;
        F4U w1; w1.f = *(const float4*)(wr + 4);
        unsigned long long wd[4] = { w0.u[0], w0.u[1], w1.u[0], w1.u[1] };
        const float* er = Es + e * EG_ST + cl;
        float4 ea = *(const float4*)er;
        float4 eb = *(const float4*)(er + 128);
        float ev[8] = { ea.x, ea.y, ea.z, ea.w, eb.x, eb.y, eb.z, eb.w };
        #pragma unroll
        for (int p = 0; p < 8; p++) {
            unsigned long long evd = pk2(ev[p], ev[p]);
            acc2[0][p] = fma2(wd[0], evd, acc2[0][p]);
            acc2[1][p] = fma2(wd[1], evd, acc2[1][p]);
            acc2[2][p] = fma2(wd[2], evd, acc2[2][p]);
            acc2[3][p] = fma2(wd[3], evd, acc2[3][p]);
        }
    }
    CP_WAIT(0);
    __syncthreads();
    #pragma unroll 4
    for (int e = 32; e < 64; e++) {
        const float* wr = Ws + e * 68 + o0;
        F4U w0; w0.f = *(const float4*)wr;
        F4U w1; w1.f = *(const float4*)(wr + 4);
        unsigned long long wd[4] = { w0.u[0], w0.u[1], w1.u[0], w1.u[1] };
        const float* er = Es + e * EG_ST + cl;
        float4 ea = *(const float4*)er;
        float4 eb = *(const float4*)(er + 128);
        float ev[8] = { ea.x, ea.y, ea.z, ea.w, eb.x, eb.y, eb.z, eb.w };
        #pragma unroll
        for (int p = 0; p < 8; p++) {
            unsigned long long evd = pk2(ev[p], ev[p]);
            acc2[0][p] = fma2(wd[0], evd, acc2[0][p]);
            acc2[1][p] = fma2(wd[1], evd, acc2[1][p]);
            acc2[2][p] = fma2(wd[2], evd, acc2[2][p]);
            acc2[3][p] = fma2(wd[3], evd, acc2[3][p]);
        }
    }

    float* ob = out + 128 * N;
    #pragma unroll
    for (int s = 0; s < 2; s++) {
        size_t c = cbase + cl + s * 128;
        int ii = (int)(c / 384), jj = (int)(c % 384);
        #pragma unroll
        for (int op = 0; op < 4; op++) {
            int oA = o0 + 2 * op, oB = oA + 1;
            float eoiA = g_hEo[oA * N + ii];
            float eoiB = g_hEo[oB * N + ii];
            float4 ejA = *(const float4*)(g_hEo + oA * N + jj);
            float4 ejB = *(const float4*)(g_hEo + oB * N + jj);
            float2 v0 = upk(acc2[op][s*4+0]);
            float2 v1 = upk(acc2[op][s*4+1]);
            float2 v2 = upk(acc2[op][s*4+2]);
            float2 v3 = upk(acc2[op][s*4+3]);
            float* pA = ob + (size_t)oA * NN + c;
            float* pB = ob + (size_t)oB * NN + c;
            *(float4*)pA = make_float4(v0.x + eoiA + ejA.x, v1.x + eoiA + ejA.y,
                                       v2.x + eoiA + ejA.z, v3.x + eoiA + ejA.w);
            *(float4*)pB = make_float4(v0.y + eoiB + ejB.x, v1.y + eoiB + ejB.y,
                                       v2.y + eoiB + ejB.z, v3.y + eoiB + ejB.w);
        }
    }
}

// ============================================================
extern "C" void kernel_launch(void* const* d_in, const int* in_sizes, int n_in,
                              void* d_out, int out_size)
{
    const float* nodes = (const float*)d_in[0];
    const float* edges = (const float*)d_in[1];
    const unsigned int* mask = (const unsigned int*)d_in[2];
    const float* Wq = (const float*)d_in[3];
    const float* Wk = (const float*)d_in[4];
    const float* Wv = (const float*)d_in[5];
    const float* Wo = (const float*)d_in[6];
    const float* We = (const float*)d_in[7];
    float* out = (float*)d_out;

    cudaFuncSetAttribute(k_edge, cudaFuncAttributeMaxDynamicSharedMemorySize, EDGE_SMEM);

    k_mk<<<17, 256>>>(Wq, Wk, Wv, mask);                 // #1
    k_prep<<<dim3(24, 12), 256>>>(nodes, Wv);            // #2
    k_attnA<<<1536, 256>>>(edges);                       // #3
    k_post<<<dim3(12, 12), 256>>>(Wo, We, out);          // #4
    k_edge<<<576, 256, EDGE_SMEM>>>(edges, We, out);     // #5
}

// round 15
// speedup vs baseline: 1.0309x; 1.0309x over previous
#include <cuda_runtime.h>
#include <math.h>

#define N   384
#define NN  (384*384)
#define JQ  96

// ---- scratch (device globals; no allocation allowed) ----
__device__ float g_Mk  [512*128];     // rs * Wk_edge^T @ Wq   [e*8+h][c]
__device__ float g_WveT[64*256];      // Wv_edge transposed    [e][hv]
__device__ float g_Qk  [384*512];     // [i][e*8+h]
__device__ float g_VnT [384*256];     // [i][hv]
__device__ float g_nfT [384*256];     // [i][hv]
__device__ float g_hEo [64*N];
__device__ float g_mask[N];
__device__ float g_part[384*4*528];   // per (i, quarter): m[8], s[8], T[8][64]

// ---- packed f32x2 helpers (Blackwell FFMA2) ----
__device__ __forceinline__ unsigned long long pk2(float a, float b) {
    unsigned long long d;
    asm("mov.b64 %0, {%1, %2};" : "=l"(d) : "f"(a), "f"(b));
    return d;
}
__device__ __forceinline__ unsigned long long fma2(unsigned long long a,
                                                   unsigned long long b,
                                                   unsigned long long c) {
    unsigned long long d;
    asm("fma.rn.f32x2 %0, %1, %2, %3;" : "=l"(d) : "l"(a), "l"(b), "l"(c));
    return d;
}
__device__ __forceinline__ float2 upk(unsigned long long v) {
    float2 r;
    asm("mov.b64 {%0, %1}, %2;" : "=f"(r.x), "=f"(r.y) : "l"(v));
    return r;
}
union F4U { float4 f; unsigned long long u[2]; };

// ---- cp.async helpers ----
__device__ __forceinline__ void cp16(void* dst, const void* src) {
    unsigned d = (unsigned)__cvta_generic_to_shared(dst);
    asm volatile("cp.async.cg.shared.global [%0], [%1], 16;" :: "r"(d), "l"(src));
}
#define CP_COMMIT() asm volatile("cp.async.commit_group;" ::: "memory")
#define CP_WAIT(n)  asm volatile("cp.async.wait_group %0;" :: "n"(n) : "memory")

// ============================================================
// Kernel 1: weights prep. Blocks 0..15: Mk = rs*Wk_edge^T@Wq.
// Block 16: WveT fill. Block 0 also decodes mask. grid(17), 256 thr.
// ============================================================
__global__ __launch_bounds__(256) void k_mk(
    const float* __restrict__ Wq,
    const float* __restrict__ Wk,
    const float* __restrict__ Wv,
    const unsigned int* __restrict__ maskw)
{
    __shared__ int s_flagF, s_flagB;
    int tid = threadIdx.x;
    const float rs = 0.17677669529663687f;

    if (blockIdx.x == 16) {
        #pragma unroll
        for (int k = 0; k < 64; k++) {
            int idx = k * 256 + tid;
            int e = idx >> 8, hv = idx & 255;
            g_WveT[idx] = Wv[hv * 192 + 128 + e];
        }
        return;
    }

    if (blockIdx.x == 0) {
        if (tid == 0) { s_flagF = 0; s_flagB = 0; }
        __syncthreads();
        if (tid < 96) {
            unsigned v = maskw[tid];
            if (v == 0x3f800000u) atomicOr(&s_flagF, 1);   // float32 1.0
            else if (v > 1u)      atomicOr(&s_flagB, 1);   // packed u8
        }
        __syncthreads();
        bool byte_mode = (!s_flagF) && s_flagB;
        for (int j = tid; j < N; j += 256) {
            float val;
            if (byte_mode) {
                unsigned w = maskw[j >> 2];
                val = ((w >> ((j & 3) * 8)) & 0xffu) ? 1.0f : 0.0f;
            } else {
                val = maskw[j] ? 1.0f : 0.0f;   // int32 or f32 bits
            }
            g_mask[j] = val;
        }
    }

    int r = blockIdx.x * 32 + (tid >> 3);
    int c0 = (tid & 7) * 16;
    int e = r >> 3, h = r & 7;
    float acc[16];
    #pragma unroll
    for (int u = 0; u < 16; u++) acc[u] = 0.f;
    #pragma unroll 4
    for (int a = 0; a < 32; a++) {
        float w = Wk[(h * 32 + a) * 192 + 128 + e];
        const float* wq = Wq + (h * 32 + a) * 128 + c0;
        #pragma unroll
        for (int u = 0; u < 16; u += 4) {
            float4 q = *(const float4*)(wq + u);
            acc[u+0] = fmaf(w, q.x, acc[u+0]);
            acc[u+1] = fmaf(w, q.y, acc[u+1]);
            acc[u+2] = fmaf(w, q.z, acc[u+2]);
            acc[u+3] = fmaf(w, q.w, acc[u+3]);
        }
    }
    #pragma unroll
    for (int u = 0; u < 16; u++) g_Mk[r * 128 + c0 + u] = rs * acc[u];
}

// ============================================================
// Kernel 2: fused GEMM [768 rows x 128k x 384 cols]:
// rows 0..511 -> g_Qk [i][r]; rows 512..767 -> g_VnT [i][hv].
// Both written COALESCED via smem-tile transpose.
// grid(24,12), 256 thr, tile 32x32.
// ============================================================
__global__ __launch_bounds__(256) void k_prep(
    const float* __restrict__ nodes,
    const float* __restrict__ Wv)
{
    __shared__ float Ws[32][33];
    __shared__ float Ns[32][36];
    int tid = threadIdx.x;
    int r0 = blockIdx.x * 32, n0 = blockIdx.y * 32;
    int co = tid & 31, ro = (tid >> 5) * 4;
    float acc[4] = {0.f, 0.f, 0.f, 0.f};

    for (int k0 = 0; k0 < 128; k0 += 32) {
        {
            int rr = tid >> 3, kl = (tid & 7) * 4;
            int r = r0 + rr;
            const float* wp = (r < 512) ? (g_Mk + r * 128) : (Wv + (r - 512) * 192);
            float4 w = *(const float4*)(wp + k0 + kl);
            Ws[rr][kl+0] = w.x; Ws[rr][kl+1] = w.y;
            Ws[rr][kl+2] = w.z; Ws[rr][kl+3] = w.w;
        }
        {
            int kk = tid >> 3, cl = (tid & 7) * 4;
            float4 v = *(const float4*)(nodes + (k0 + kk) * N + n0 + cl);
            Ns[kk][cl+0] = v.x; Ns[kk][cl+1] = v.y;
            Ns[kk][cl+2] = v.z; Ns[kk][cl+3] = v.w;
        }
        __syncthreads();
        #pragma unroll
        for (int k = 0; k < 32; k++) {
            float ev = Ns[k][co];
            acc[0] = fmaf(Ws[ro+0][k], ev, acc[0]);
            acc[1] = fmaf(Ws[ro+1][k], ev, acc[1]);
            acc[2] = fmaf(Ws[ro+2][k], ev, acc[2]);
            acc[3] = fmaf(Ws[ro+3][k], ev, acc[3]);
        }
        __syncthreads();
    }

    // stage to smem (reuse Ns) then write transposed, coalesced
    #pragma unroll
    for (int q = 0; q < 4; q++) Ns[ro + q][co] = acc[q];
    __syncthreads();

    int i_loc = tid >> 3, rl = (tid & 7) * 4;
    float4 o = make_float4(Ns[rl][i_loc], Ns[rl+1][i_loc],
                           Ns[rl+2][i_loc], Ns[rl+3][i_loc]);
    if (r0 < 512)
        *(float4*)(g_Qk  + (size_t)(n0 + i_loc) * 512 + r0 + rl) = o;
    else
        *(float4*)(g_VnT + (size_t)(n0 + i_loc) * 256 + (r0 - 512) + rl) = o;
}

// ============================================================
// Kernel 3: attention partials (R13-proven). grid(1536) = 384 i x
// 4 quarters, 256 thr, ~35KB static smem. cp.async split staging.
// ============================================================
#define ES_ST 100
#define PH_ST 100
#define P2W   196

__global__ __launch_bounds__(256) void k_attnA(const float* __restrict__ edges)
{
    __shared__ float Es[64 * ES_ST];
    __shared__ float s_ph[8 * PH_ST];
    __shared__ float p2f[4 * P2W];
    __shared__ float s_Qk[512];
    __shared__ float s_mf[JQ];
    __shared__ float s_ms[16];

    int bx = blockIdx.x;
    int i = bx >> 2, qn = bx & 3, jb = qn * JQ;
    int tid = threadIdx.x, lane = tid & 31, wid = tid >> 5;

    // cp.async staging, two 32-e chunks. 64 x 24 float4 = 1536; 6/thread.
    const float* erow = edges + (size_t)i * N + jb;
    #pragma unroll
    for (int it = 0; it < 3; it++) {
        int idx = it * 256 + tid;
        int e = idx / 24, c4 = idx - e * 24;
        cp16(&Es[e * ES_ST + c4 * 4], erow + (size_t)e * NN + c4 * 4);
    }
    CP_COMMIT();
    #pragma unroll
    for (int it = 3; it < 6; it++) {
        int idx = it * 256 + tid;
        int e = idx / 24, c4 = idx - e * 24;
        cp16(&Es[e * ES_ST + c4 * 4], erow + (size_t)e * NN + c4 * 4);
    }
    CP_COMMIT();

    s_Qk[tid]       = g_Qk[(size_t)i * 512 + tid];
    s_Qk[256 + tid] = g_Qk[(size_t)i * 512 + 256 + tid];
    if (tid < JQ) s_mf[tid] = g_mask[jb + tid];

    // pass 1: sim. thread = (jg of 48, hh of 2). 96 active threads.
    unsigned long long acc2[4] = {0ull, 0ull, 0ull, 0ull};
    int jg = tid >> 1, hh = tid & 1, j0 = jg * 2;
    const float* ep = Es + j0;
    const float* qp = s_Qk + hh * 4;

    CP_WAIT(1);
    __syncthreads();
    if (tid < 2 * 48) {
        #pragma unroll 8
        for (int e = 0; e < 32; e++) {
            float2 ev = *(const float2*)(ep + e * ES_ST);
            unsigned long long ed0 = pk2(ev.x, ev.x);
            unsigned long long ed1 = pk2(ev.y, ev.y);
            F4U q; q.f = *(const float4*)(qp + e * 8);
            acc2[0] = fma2(q.u[0], ed0, acc2[0]);
            acc2[1] = fma2(q.u[1], ed0, acc2[1]);
            acc2[2] = fma2(q.u[0], ed1, acc2[2]);
            acc2[3] = fma2(q.u[1], ed1, acc2[3]);
        }
    }
    CP_WAIT(0);
    __syncthreads();
    if (tid < 2 * 48) {
        #pragma unroll 8
        for (int e = 32; e < 64; e++) {
            float2 ev = *(const float2*)(ep + e * ES_ST);
            unsigned long long ed0 = pk2(ev.x, ev.x);
            unsigned long long ed1 = pk2(ev.y, ev.y);
            F4U q; q.f = *(const float4*)(qp + e * 8);
            acc2[0] = fma2(q.u[0], ed0, acc2[0]);
            acc2[1] = fma2(q.u[1], ed0, acc2[1]);
            acc2[2] = fma2(q.u[0], ed1, acc2[2]);
            acc2[3] = fma2(q.u[1], ed1, acc2[3]);
        }
        float m0 = (s_mf[j0]     > 0.f) ? 0.f : 1.f;
        float m1 = (s_mf[j0 + 1] > 0.f) ? 0.f : 1.f;
        float2 a0 = upk(acc2[0]), a1 = upk(acc2[1]);
        float2 b0 = upk(acc2[2]), b1 = upk(acc2[3]);
        int hb = hh * 4;
        s_ph[(hb+0)*PH_ST + j0] = m0 ? -INFINITY : a0.x;
        s_ph[(hb+1)*PH_ST + j0] = m0 ? -INFINITY : a0.y;
        s_ph[(hb+2)*PH_ST + j0] = m0 ? -INFINITY : a1.x;
        s_ph[(hb+3)*PH_ST + j0] = m0 ? -INFINITY : a1.y;
        s_ph[(hb+0)*PH_ST + j0+1] = m1 ? -INFINITY : b0.x;
        s_ph[(hb+1)*PH_ST + j0+1] = m1 ? -INFINITY : b0.y;
        s_ph[(hb+2)*PH_ST + j0+1] = m1 ? -INFINITY : b1.x;
        s_ph[(hb+3)*PH_ST + j0+1] = m1 ? -INFINITY : b1.y;
    }
    __syncthreads();

    // local softmax stats: warp h owns row h
    {
        int h = wid;
        float* row = s_ph + h * PH_ST;
        float m = -INFINITY;
        #pragma unroll
        for (int jl = lane; jl < JQ; jl += 32) m = fmaxf(m, row[jl]);
        #pragma unroll
        for (int o = 16; o; o >>= 1) m = fmaxf(m, __shfl_xor_sync(0xffffffffu, m, o));
        float mexp = (m == -INFINITY) ? 0.f : m;
        float sum = 0.f;
        #pragma unroll
        for (int jl = lane; jl < JQ; jl += 32) {
            float ev = __expf(row[jl] - mexp);
            row[jl] = ev;
            sum += ev;
        }
        #pragma unroll
        for (int o = 16; o; o >>= 1) sum += __shfl_xor_sync(0xffffffffu, sum, o);
        if (lane == 0) { s_ms[h] = m; s_ms[8 + h] = sum; }
    }
    __syncthreads();

    // repack raw exp into h-pair float2 rows (384 items)
    #pragma unroll
    for (int k = 0; k < 2; k++) {
        int idx = k * 256 + tid;
        if (idx < 4 * JQ) {
            int hp = idx / JQ, j = idx - hp * JQ;
            float x = s_ph[(2*hp)   * PH_ST + j];
            float y = s_ph[(2*hp+1) * PH_ST + j];
            *(float2*)&p2f[hp * P2W + 2*j] = make_float2(x, y);
        }
    }
    __syncthreads();

    // pass 2: T[2hp..2hp+1][e] owned entirely by thread (e, hp)
    float* gp = g_part + ((size_t)i * 4 + qn) * 528;
    {
        int e = tid >> 2, hp = tid & 3;
        const float* epp = Es + e * ES_ST;
        const float* pp = p2f + hp * P2W;
        unsigned long long t2[4] = {0ull, 0ull, 0ull, 0ull};
        #pragma unroll 6
        for (int j = 0; j < JQ; j += 4) {
            float4 ev4 = *(const float4*)(epp + j);
            F4U pA; pA.f = *(const float4*)(pp + 2*j);
            F4U pB; pB.f = *(const float4*)(pp + 2*j + 4);
            t2[0] = fma2(pA.u[0], pk2(ev4.x, ev4.x), t2[0]);
            t2[1] = fma2(pA.u[1], pk2(ev4.y, ev4.y), t2[1]);
            t2[2] = fma2(pB.u[0], pk2(ev4.z, ev4.z), t2[2]);
            t2[3] = fma2(pB.u[1], pk2(ev4.w, ev4.w), t2[3]);
        }
        float2 t0 = upk(t2[0]), t1 = upk(t2[1]);
        float2 t3 = upk(t2[2]), t4 = upk(t2[3]);
        gp[16 + (2*hp)   * 64 + e] = (t0.x + t1.x) + (t3.x + t4.x);
        gp[16 + (2*hp+1) * 64 + e] = (t0.y + t1.y) + (t3.y + t4.y);
    }
    if (tid < 16) gp[tid] = s_ms[tid];
}

// ============================================================
// Kernel 4: combine 4 quarters -> node_features (coalesced).
// grid(384), 256 thr.
// ============================================================
__global__ __launch_bounds__(256) void k_attnB()
{
    __shared__ float s_T[512];
    __shared__ float s_fac[32];
    int i = blockIdx.x;
    int tid = threadIdx.x;
    float maski = g_mask[i];
    const float* gp = g_part + (size_t)i * 4 * 528;

    if (tid < 32) {
        int q = tid >> 3, h = tid & 7;
        float m = gp[q * 528 + h];
        float s = gp[q * 528 + 8 + h];
        float mg = m;
        mg = fmaxf(mg, __shfl_xor_sync(0xffffffffu, mg, 8));
        mg = fmaxf(mg, __shfl_xor_sync(0xffffffffu, mg, 16));
        float mg2 = (mg == -INFINITY) ? 0.f : mg;
        float w = s * __expf(m - mg2);
        float tot = w;
        tot += __shfl_xor_sync(0xffffffffu, tot, 8);
        tot += __shfl_xor_sync(0xffffffffu, tot, 16);
        s_fac[q * 8 + h] = __expf(m - mg2) * maski / tot;
    }
    __syncthreads();

    #pragma unroll
    for (int r = 0; r < 2; r++) {
        int idx = r * 256 + tid;
        int h = idx >> 6;
        float a = fmaf(s_fac[h],      gp[16 + idx],
                  s_fac[8 + h]  * gp[528 + 16 + idx]);
        float b = fmaf(s_fac[16 + h], gp[1056 + 16 + idx],
                  s_fac[24 + h] * gp[1584 + 16 + idx]);
        s_T[idx] = a + b;
    }
    __syncthreads();

    {
        int hv = tid, h = hv >> 5;
        const float* st = s_T + h * 64;
        float a0 = g_VnT[(size_t)i * 256 + hv] * maski;
        float a1 = 0.f;
        #pragma unroll 8
        for (int e = 0; e < 64; e += 2) {
            a0 = fmaf(g_WveT[e * 256 + hv],       st[e],     a0);
            a1 = fmaf(g_WveT[(e + 1) * 256 + hv], st[e + 1], a1);
        }
        g_nfT[(size_t)i * 256 + hv] = a0 + a1;
    }
}

// ============================================================
// Kernel 5: node_out = Wo@nf ; hEo = 0.5*We[:,:256]@nf
// grid(24,12) = 288 CTAs (~2/SM), tile 8 rows x 32 cols,
// register-prefetch double buffer. Reads g_nfT [i][hv].
// ============================================================
__global__ __launch_bounds__(256) void k_post(
    const float* __restrict__ Wo,
    const float* __restrict__ We,
    float* __restrict__ out)
{
    __shared__ float Ws[8][33];
    __shared__ float Ns[32][36];
    int tid = threadIdx.x;
    int r0 = blockIdx.x * 8, n0 = blockIdx.y * 32;
    int co = tid & 31, ro = tid >> 5;
    float acc = 0.f;

    int wr = tid >> 5, wk = tid & 31;           // weights: 8 rows x 32 k, 1/thread
    int n_loc = tid >> 3, kkl = (tid & 7) * 4;  // nfT: 32 n x 32 k as float4
    const float* wp;
    {
        int r = r0 + wr;
        wp = (r < 128) ? (Wo + r * 256) : (We + (r - 128) * 320);
    }

    float wreg = wp[wk];
    float4 nreg = *(const float4*)(g_nfT + (size_t)(n0 + n_loc) * 256 + kkl);

    for (int k0 = 0; k0 < 256; k0 += 32) {
        Ws[wr][wk] = wreg;
        Ns[kkl+0][n_loc] = nreg.x; Ns[kkl+1][n_loc] = nreg.y;
        Ns[kkl+2][n_loc] = nreg.z; Ns[kkl+3][n_loc] = nreg.w;
        __syncthreads();
        if (k0 < 224) {
            wreg = wp[k0 + 32 + wk];
            nreg = *(const float4*)(g_nfT + (size_t)(n0 + n_loc) * 256 + k0 + 32 + kkl);
        }
        #pragma unroll
        for (int k = 0; k < 32; k++)
            acc = fmaf(Ws[ro][k], Ns[k][co], acc);
        __syncthreads();
    }
    {
        int rq = r0 + ro;
        if (rq < 128) out[rq * N + n0 + co] = acc;
        else          g_hEo[(rq - 128) * N + n0 + co] = 0.5f * acc;
    }
}

// ============================================================
// Kernel 6: edge_out (R13-proven). grid(576), 256 thr, 2 CTAs/SM.
// CTA tile 64o x 256c, thread 8o x 8c, FFMA2 o-pairs, cp.async.
// ============================================================
#define EG_ST 260
#define EDGE_SMEM ((64*68 + 64*EG_ST) * 4)

__global__ __launch_bounds__(256, 2) void k_edge(
    const float* __restrict__ edges,
    const float* __restrict__ We,
    float* __restrict__ out)
{
    extern __shared__ float esm[];
    float* Ws = esm;              // [64][68]  Ws[e][o]
    float* Es = esm + 64 * 68;    // [64][260]

    int tid = threadIdx.x, lane = tid & 31, wid = tid >> 5;
    size_t cbase = (size_t)blockIdx.x * 256;

    #pragma unroll
    for (int it = 0; it < 8; it++) {
        int idx = it * 256 + tid;
        int e = idx >> 6, c4 = idx & 63;
        cp16(&Es[e * EG_ST + c4 * 4], edges + (size_t)e * NN + cbase + c4 * 4);
    }
    CP_COMMIT();
    #pragma unroll
    for (int it = 8; it < 16; it++) {
        int idx = it * 256 + tid;
        int e = idx >> 6, c4 = idx & 63;
        cp16(&Es[e * EG_ST + c4 * 4], edges + (size_t)e * NN + cbase + c4 * 4);
    }
    CP_COMMIT();

    {
        int o = tid >> 2, e0 = (tid & 3) * 16;
        const float* wp = We + o * 320 + 256 + e0;
        #pragma unroll
        for (int u = 0; u < 16; u += 4) {
            float4 w = *(const float4*)(wp + u);
            Ws[(e0+u+0)*68 + o] = w.x; Ws[(e0+u+1)*68 + o] = w.y;
            Ws[(e0+u+2)*68 + o] = w.z; Ws[(e0+u+3)*68 + o] = w.w;
        }
    }

    int o0 = wid * 8;
    int cl = lane * 4;

    unsigned long long acc2[4][8];
    #pragma unroll
    for (int op = 0; op < 4; op++)
        #pragma unroll
        for (int p = 0; p < 8; p++) acc2[op][p] = 0ull;

    CP_WAIT(1);
    __syncthreads();
    #pragma unroll 4
    for (int e = 0; e < 32; e++) {
        const float* wr = Ws + e * 68 + o0;
        F4U w0; w0.f = *(const float4*)wr;
        F4U w1; w1.f = *(const float4*)(wr + 4);
        unsigned long long wd[4] = { w0.u[0], w0.u[1], w1.u[0], w1.u[1] };
        const float* er = Es + e * EG_ST + cl;
        float4 ea = *(const float4*)er;
        float4 eb = *(const float4*)(er + 128);
        float ev[8] = { ea.x, ea.y, ea.z, ea.w, eb.x, eb.y, eb.z, eb.w };
        #pragma unroll
        for (int p = 0; p < 8; p++) {
            unsigned long long evd = pk2(ev[p], ev[p]);
            acc2[0][p] = fma2(wd[0], evd, acc2[0][p]);
            acc2[1][p] = fma2(wd[1], evd, acc2[1][p]);
            acc2[2][p] = fma2(wd[2], evd, acc2[2][p]);
            acc2[3][p] = fma2(wd[3], evd, acc2[3][p]);
        }
    }
    CP_WAIT(0);
    __syncthreads();
    #pragma unroll 4
    for (int e = 32; e < 64; e++) {
        const float* wr = Ws + e * 68 + o0;
        F4U w0; w0.f = *(const float4*)wr;
        F4U w1; w1.f = *(const float4*)(wr + 4);
        unsigned long long wd[4] = { w0.u[0], w0.u[1], w1.u[0], w1.u[1] };
        const float* er = Es + e * EG_ST + cl;
        float4 ea = *(const float4*)er;
        float4 eb = *(const float4*)(er + 128);
        float ev[8] = { ea.x, ea.y, ea.z, ea.w, eb.x, eb.y, eb.z, eb.w };
        #pragma unroll
        for (int p = 0; p < 8; p++) {
            unsigned long long evd = pk2(ev[p], ev[p]);
            acc2[0][p] = fma2(wd[0], evd, acc2[0][p]);
            acc2[1][p] = fma2(wd[1], evd, acc2[1][p]);
            acc2[2][p] = fma2(wd[2], evd, acc2[2][p]);
            acc2[3][p] = fma2(wd[3], evd, acc2[3][p]);
        }
    }

    float* ob = out + 128 * N;
    #pragma unroll
    for (int s = 0; s < 2; s++) {
        size_t c = cbase + cl + s * 128;
        int ii = (int)(c / 384), jj = (int)(c % 384);
        #pragma unroll
        for (int op = 0; op < 4; op++) {
            int oA = o0 + 2 * op, oB = oA + 1;
            float eoiA = g_hEo[oA * N + ii];
            float eoiB = g_hEo[oB * N + ii];
            float4 ejA = *(const float4*)(g_hEo + oA * N + jj);
            float4 ejB = *(const float4*)(g_hEo + oB * N + jj);
            float2 v0 = upk(acc2[op][s*4+0]);
            float2 v1 = upk(acc2[op][s*4+1]);
            float2 v2 = upk(acc2[op][s*4+2]);
            float2 v3 = upk(acc2[op][s*4+3]);
            float* pA = ob + (size_t)oA * NN + c;
            float* pB = ob + (size_t)oB * NN + c;
            *(float4*)pA = make_float4(v0.x + eoiA + ejA.x, v1.x + eoiA + ejA.y,
                                       v2.x + eoiA + ejA.z, v3.x + eoiA + ejA.w);
            *(float4*)pB = make_float4(v0.y + eoiB + ejB.x, v1.y + eoiB + ejB.y,
                                       v2.y + eoiB + ejB.z, v3.y + eoiB + ejB.w);
        }
    }
}

// ============================================================
extern "C" void kernel_launch(void* const* d_in, const int* in_sizes, int n_in,
                              void* d_out, int out_size)
{
    const float* nodes = (const float*)d_in[0];
    const float* edges = (const float*)d_in[1];
    const unsigned int* mask = (const unsigned int*)d_in[2];
    const float* Wq = (const float*)d_in[3];
    const float* Wk = (const float*)d_in[4];
    const float* Wv = (const float*)d_in[5];
    const float* Wo = (const float*)d_in[6];
    const float* We = (const float*)d_in[7];
    float* out = (float*)d_out;

    cudaFuncSetAttribute(k_edge, cudaFuncAttributeMaxDynamicSharedMemorySize, EDGE_SMEM);

    k_mk<<<17, 256>>>(Wq, Wk, Wv, mask);                 // #1
    k_prep<<<dim3(24, 12), 256>>>(nodes, Wv);            // #2
    k_attnA<<<1536, 256>>>(edges);                       // #3
    k_attnB<<<384, 256>>>();                             // #4
    k_post<<<dim3(24, 12), 256>>>(Wo, We, out);          // #5
    k_edge<<<576, 256, EDGE_SMEM>>>(edges, We, out);     // #6
}

// round 16
// speedup vs baseline: 1.0713x; 1.0392x over previous
#include <cuda_runtime.h>
#include <math.h>

#define N   384
#define NN  (384*384)
#define JQ  96

// ---- scratch (device globals; no allocation allowed) ----
__device__ float g_WveT[64*256];      // Wv_edge transposed    [e][hv]
__device__ float g_WT  [256*192];     // [k][r]: r<128 Wo, r>=128 We[:, :256]
__device__ float g_Qk  [384*512];     // [i][e*8+h]
__device__ float g_VnT [384*256];     // [i][hv]
__device__ float g_hEo [64*N];
__device__ float g_mask[N];
__device__ float g_part[384*4*528];   // per (i, quarter): m[8], s[8], T[8][64]

// ---- packed f32x2 helpers (Blackwell FFMA2) ----
__device__ __forceinline__ unsigned long long pk2(float a, float b) {
    unsigned long long d;
    asm("mov.b64 %0, {%1, %2};" : "=l"(d) : "f"(a), "f"(b));
    return d;
}
__device__ __forceinline__ unsigned long long fma2(unsigned long long a,
                                                   unsigned long long b,
                                                   unsigned long long c) {
    unsigned long long d;
    asm("fma.rn.f32x2 %0, %1, %2, %3;" : "=l"(d) : "l"(a), "l"(b), "l"(c));
    return d;
}
__device__ __forceinline__ float2 upk(unsigned long long v) {
    float2 r;
    asm("mov.b64 {%0, %1}, %2;" : "=f"(r.x), "=f"(r.y) : "l"(v));
    return r;
}
union F4U { float4 f; unsigned long long u[2]; };

// ---- cp.async helpers ----
__device__ __forceinline__ void cp16(void* dst, const void* src) {
    unsigned d = (unsigned)__cvta_generic_to_shared(dst);
    asm volatile("cp.async.cg.shared.global [%0], [%1], 16;" :: "r"(d), "l"(src));
}
#define CP_COMMIT() asm volatile("cp.async.commit_group;" ::: "memory")
#define CP_WAIT(n)  asm volatile("cp.async.wait_group %0;" :: "n"(n) : "memory")

// ============================================================
// Kernel 1: mega-prep. grid(25,12), 256 thr.
//  x<16 : Qk rows — inline Mk tile (rs*Wk_edge^T@Wq) in smem,
//         then GEMM vs nodes, transpose-store to g_Qk [i][r].
//  x=16..23 : Vn rows (Wv[:, :128] @ nodes) -> g_VnT [i][hv].
//  x=24 : weight transposes (WveT, WT) + mask decode (y==0).
// ============================================================
__global__ __launch_bounds__(256) void k_prep(
    const float* __restrict__ nodes,
    const float* __restrict__ Wq,
    const float* __restrict__ Wk,
    const float* __restrict__ Wv,
    const float* __restrict__ Wo,
    const float* __restrict__ We,
    const unsigned int* __restrict__ maskw)
{
    __shared__ float sMk[32][132];
    __shared__ float Ws[32][33];
    __shared__ float Ns[32][36];
    __shared__ int s_flagF, s_flagB;
    int tid = threadIdx.x;
    const float rs = 0.17677669529663687f;

    if (blockIdx.x == 24) {
        if (blockIdx.y == 0) {
            // mask decode
            if (tid == 0) { s_flagF = 0; s_flagB = 0; }
            __syncthreads();
            if (tid < 96) {
                unsigned v = maskw[tid];
                if (v == 0x3f800000u) atomicOr(&s_flagF, 1);   // float32 1.0
                else if (v > 1u)      atomicOr(&s_flagB, 1);   // packed u8
            }
            __syncthreads();
            bool byte_mode = (!s_flagF) && s_flagB;
            for (int j = tid; j < N; j += 256) {
                float val;
                if (byte_mode) {
                    unsigned w = maskw[j >> 2];
                    val = ((w >> ((j & 3) * 8)) & 0xffu) ? 1.0f : 0.0f;
                } else {
                    val = maskw[j] ? 1.0f : 0.0f;
                }
                g_mask[j] = val;
            }
            // WveT[e][hv]
            #pragma unroll
            for (int k = 0; k < 64; k++) {
                int idx = k * 256 + tid;
                int e = idx >> 8, hv = idx & 255;
                g_WveT[idx] = Wv[hv * 192 + 128 + e];
            }
        } else {
            // WT[k][r] fill: 49152 elems over 11 blocks
            for (int idx = (blockIdx.y - 1) * 256 + tid; idx < 256 * 192;
                 idx += 11 * 256) {
                int k = idx / 192, r = idx - k * 192;
                g_WT[idx] = (r < 128) ? Wo[r * 256 + k]
                                      : We[(r - 128) * 320 + k];
            }
        }
        return;
    }

    int r0 = blockIdx.x * 32, n0 = blockIdx.y * 32;
    int co = tid & 31, ro = (tid >> 5) * 4;
    float acc[4] = {0.f, 0.f, 0.f, 0.f};
    bool qk_path = (r0 < 512);

    if (qk_path) {
        // inline Mk tile: sMk[rr][c] = rs * sum_a Wk[(h*32+a)*192+128+e]*Wq[(h*32+a)*128+c]
        int rr = tid >> 3, c0 = (tid & 7) * 16;
        int r = r0 + rr, e = r >> 3, h = r & 7;
        float a16[16];
        #pragma unroll
        for (int u = 0; u < 16; u++) a16[u] = 0.f;
        #pragma unroll 4
        for (int a = 0; a < 32; a++) {
            float w = Wk[(h * 32 + a) * 192 + 128 + e];
            const float* wq = Wq + (h * 32 + a) * 128 + c0;
            #pragma unroll
            for (int u = 0; u < 16; u += 4) {
                float4 q = *(const float4*)(wq + u);
                a16[u+0] = fmaf(w, q.x, a16[u+0]);
                a16[u+1] = fmaf(w, q.y, a16[u+1]);
                a16[u+2] = fmaf(w, q.z, a16[u+2]);
                a16[u+3] = fmaf(w, q.w, a16[u+3]);
            }
        }
        #pragma unroll
        for (int u = 0; u < 16; u++) sMk[rr][c0 + u] = rs * a16[u];
        __syncthreads();

        for (int k0 = 0; k0 < 128; k0 += 32) {
            {
                int kk = tid >> 3, cl = (tid & 7) * 4;
                float4 v = *(const float4*)(nodes + (k0 + kk) * N + n0 + cl);
                Ns[kk][cl+0] = v.x; Ns[kk][cl+1] = v.y;
                Ns[kk][cl+2] = v.z; Ns[kk][cl+3] = v.w;
            }
            __syncthreads();
            #pragma unroll
            for (int k = 0; k < 32; k++) {
                float ev = Ns[k][co];
                acc[0] = fmaf(sMk[ro+0][k0+k], ev, acc[0]);
                acc[1] = fmaf(sMk[ro+1][k0+k], ev, acc[1]);
                acc[2] = fmaf(sMk[ro+2][k0+k], ev, acc[2]);
                acc[3] = fmaf(sMk[ro+3][k0+k], ev, acc[3]);
            }
            __syncthreads();
        }
    } else {
        for (int k0 = 0; k0 < 128; k0 += 32) {
            {
                int rr = tid >> 3, kl = (tid & 7) * 4;
                float4 w = *(const float4*)(Wv + (r0 - 512 + rr) * 192 + k0 + kl);
                Ws[rr][kl+0] = w.x; Ws[rr][kl+1] = w.y;
                Ws[rr][kl+2] = w.z; Ws[rr][kl+3] = w.w;
            }
            {
                int kk = tid >> 3, cl = (tid & 7) * 4;
                float4 v = *(const float4*)(nodes + (k0 + kk) * N + n0 + cl);
                Ns[kk][cl+0] = v.x; Ns[kk][cl+1] = v.y;
                Ns[kk][cl+2] = v.z; Ns[kk][cl+3] = v.w;
            }
            __syncthreads();
            #pragma unroll
            for (int k = 0; k < 32; k++) {
                float ev = Ns[k][co];
                acc[0] = fmaf(Ws[ro+0][k], ev, acc[0]);
                acc[1] = fmaf(Ws[ro+1][k], ev, acc[1]);
                acc[2] = fmaf(Ws[ro+2][k], ev, acc[2]);
                acc[3] = fmaf(Ws[ro+3][k], ev, acc[3]);
            }
            __syncthreads();
        }
    }

    // stage to smem (reuse Ns) then write transposed, coalesced
    #pragma unroll
    for (int q = 0; q < 4; q++) Ns[ro + q][co] = acc[q];
    __syncthreads();

    int i_loc = tid >> 3, rl = (tid & 7) * 4;
    float4 o = make_float4(Ns[rl][i_loc], Ns[rl+1][i_loc],
                           Ns[rl+2][i_loc], Ns[rl+3][i_loc]);
    if (qk_path)
        *(float4*)(g_Qk  + (size_t)(n0 + i_loc) * 512 + r0 + rl) = o;
    else
        *(float4*)(g_VnT + (size_t)(n0 + i_loc) * 256 + (r0 - 512) + rl) = o;
}

// ============================================================
// Kernel 2: attention partials (R13-proven). grid(1536) = 384 i x
// 4 quarters, 256 thr, ~35KB static smem. cp.async split staging.
// ============================================================
#define ES_ST 100
#define PH_ST 100
#define P2W   196

__global__ __launch_bounds__(256) void k_attnA(const float* __restrict__ edges)
{
    __shared__ float Es[64 * ES_ST];
    __shared__ float s_ph[8 * PH_ST];
    __shared__ float p2f[4 * P2W];
    __shared__ float s_Qk[512];
    __shared__ float s_mf[JQ];
    __shared__ float s_ms[16];

    int bx = blockIdx.x;
    int i = bx >> 2, qn = bx & 3, jb = qn * JQ;
    int tid = threadIdx.x, lane = tid & 31, wid = tid >> 5;

    const float* erow = edges + (size_t)i * N + jb;
    #pragma unroll
    for (int it = 0; it < 3; it++) {
        int idx = it * 256 + tid;
        int e = idx / 24, c4 = idx - e * 24;
        cp16(&Es[e * ES_ST + c4 * 4], erow + (size_t)e * NN + c4 * 4);
    }
    CP_COMMIT();
    #pragma unroll
    for (int it = 3; it < 6; it++) {
        int idx = it * 256 + tid;
        int e = idx / 24, c4 = idx - e * 24;
        cp16(&Es[e * ES_ST + c4 * 4], erow + (size_t)e * NN + c4 * 4);
    }
    CP_COMMIT();

    s_Qk[tid]       = g_Qk[(size_t)i * 512 + tid];
    s_Qk[256 + tid] = g_Qk[(size_t)i * 512 + 256 + tid];
    if (tid < JQ) s_mf[tid] = g_mask[jb + tid];

    unsigned long long acc2[4] = {0ull, 0ull, 0ull, 0ull};
    int jg = tid >> 1, hh = tid & 1, j0 = jg * 2;
    const float* ep = Es + j0;
    const float* qp = s_Qk + hh * 4;

    CP_WAIT(1);
    __syncthreads();
    if (tid < 2 * 48) {
        #pragma unroll 8
        for (int e = 0; e < 32; e++) {
            float2 ev = *(const float2*)(ep + e * ES_ST);
            unsigned long long ed0 = pk2(ev.x, ev.x);
            unsigned long long ed1 = pk2(ev.y, ev.y);
            F4U q; q.f = *(const float4*)(qp + e * 8);
            acc2[0] = fma2(q.u[0], ed0, acc2[0]);
            acc2[1] = fma2(q.u[1], ed0, acc2[1]);
            acc2[2] = fma2(q.u[0], ed1, acc2[2]);
            acc2[3] = fma2(q.u[1], ed1, acc2[3]);
        }
    }
    CP_WAIT(0);
    __syncthreads();
    if (tid < 2 * 48) {
        #pragma unroll 8
        for (int e = 32; e < 64; e++) {
            float2 ev = *(const float2*)(ep + e * ES_ST);
            unsigned long long ed0 = pk2(ev.x, ev.x);
            unsigned long long ed1 = pk2(ev.y, ev.y);
            F4U q; q.f = *(const float4*)(qp + e * 8);
            acc2[0] = fma2(q.u[0], ed0, acc2[0]);
            acc2[1] = fma2(q.u[1], ed0, acc2[1]);
            acc2[2] = fma2(q.u[0], ed1, acc2[2]);
            acc2[3] = fma2(q.u[1], ed1, acc2[3]);
        }
        float m0 = (s_mf[j0]     > 0.f) ? 0.f : 1.f;
        float m1 = (s_mf[j0 + 1] > 0.f) ? 0.f : 1.f;
        float2 a0 = upk(acc2[0]), a1 = upk(acc2[1]);
        float2 b0 = upk(acc2[2]), b1 = upk(acc2[3]);
        int hb = hh * 4;
        s_ph[(hb+0)*PH_ST + j0] = m0 ? -INFINITY : a0.x;
        s_ph[(hb+1)*PH_ST + j0] = m0 ? -INFINITY : a0.y;
        s_ph[(hb+2)*PH_ST + j0] = m0 ? -INFINITY : a1.x;
        s_ph[(hb+3)*PH_ST + j0] = m0 ? -INFINITY : a1.y;
        s_ph[(hb+0)*PH_ST + j0+1] = m1 ? -INFINITY : b0.x;
        s_ph[(hb+1)*PH_ST + j0+1] = m1 ? -INFINITY : b0.y;
        s_ph[(hb+2)*PH_ST + j0+1] = m1 ? -INFINITY : b1.x;
        s_ph[(hb+3)*PH_ST + j0+1] = m1 ? -INFINITY : b1.y;
    }
    __syncthreads();

    {
        int h = wid;
        float* row = s_ph + h * PH_ST;
        float m = -INFINITY;
        #pragma unroll
        for (int jl = lane; jl < JQ; jl += 32) m = fmaxf(m, row[jl]);
        #pragma unroll
        for (int o = 16; o; o >>= 1) m = fmaxf(m, __shfl_xor_sync(0xffffffffu, m, o));
        float mexp = (m == -INFINITY) ? 0.f : m;
        float sum = 0.f;
        #pragma unroll
        for (int jl = lane; jl < JQ; jl += 32) {
            float ev = __expf(row[jl] - mexp);
            row[jl] = ev;
            sum += ev;
        }
        #pragma unroll
        for (int o = 16; o; o >>= 1) sum += __shfl_xor_sync(0xffffffffu, sum, o);
        if (lane == 0) { s_ms[h] = m; s_ms[8 + h] = sum; }
    }
    __syncthreads();

    #pragma unroll
    for (int k = 0; k < 2; k++) {
        int idx = k * 256 + tid;
        if (idx < 4 * JQ) {
            int hp = idx / JQ, j = idx - hp * JQ;
            float x = s_ph[(2*hp)   * PH_ST + j];
            float y = s_ph[(2*hp+1) * PH_ST + j];
            *(float2*)&p2f[hp * P2W + 2*j] = make_float2(x, y);
        }
    }
    __syncthreads();

    float* gp = g_part + ((size_t)i * 4 + qn) * 528;
    {
        int e = tid >> 2, hp = tid & 3;
        const float* epp = Es + e * ES_ST;
        const float* pp = p2f + hp * P2W;
        unsigned long long t2[4] = {0ull, 0ull, 0ull, 0ull};
        #pragma unroll 6
        for (int j = 0; j < JQ; j += 4) {
            float4 ev4 = *(const float4*)(epp + j);
            F4U pA; pA.f = *(const float4*)(pp + 2*j);
            F4U pB; pB.f = *(const float4*)(pp + 2*j + 4);
            t2[0] = fma2(pA.u[0], pk2(ev4.x, ev4.x), t2[0]);
            t2[1] = fma2(pA.u[1], pk2(ev4.y, ev4.y), t2[1]);
            t2[2] = fma2(pB.u[0], pk2(ev4.z, ev4.z), t2[2]);
            t2[3] = fma2(pB.u[1], pk2(ev4.w, ev4.w), t2[3]);
        }
        float2 t0 = upk(t2[0]), t1 = upk(t2[1]);
        float2 t3 = upk(t2[2]), t4 = upk(t2[3]);
        gp[16 + (2*hp)   * 64 + e] = (t0.x + t1.x) + (t3.x + t4.x);
        gp[16 + (2*hp+1) * 64 + e] = (t0.y + t1.y) + (t3.y + t4.y);
    }
    if (tid < 16) gp[tid] = s_ms[tid];
}

// ============================================================
// Kernel 3: combine quarters -> nf (smem) -> node_out + hEo.
// grid(384), 256 thr. Fuses former attnB + k_post.
// ============================================================
__global__ __launch_bounds__(256) void k_attnB(float* __restrict__ out)
{
    __shared__ float s_T[512];
    __shared__ float s_fac[32];
    __shared__ float s_nf[256];
    int i = blockIdx.x;
    int tid = threadIdx.x;
    float maski = g_mask[i];
    const float* gp = g_part + (size_t)i * 4 * 528;

    if (tid < 32) {
        int q = tid >> 3, h = tid & 7;
        float m = gp[q * 528 + h];
        float s = gp[q * 528 + 8 + h];
        float mg = m;
        mg = fmaxf(mg, __shfl_xor_sync(0xffffffffu, mg, 8));
        mg = fmaxf(mg, __shfl_xor_sync(0xffffffffu, mg, 16));
        float mg2 = (mg == -INFINITY) ? 0.f : mg;
        float w = s * __expf(m - mg2);
        float tot = w;
        tot += __shfl_xor_sync(0xffffffffu, tot, 8);
        tot += __shfl_xor_sync(0xffffffffu, tot, 16);
        s_fac[q * 8 + h] = __expf(m - mg2) * maski / tot;
    }
    __syncthreads();

    #pragma unroll
    for (int r = 0; r < 2; r++) {
        int idx = r * 256 + tid;
        int h = idx >> 6;
        float a = fmaf(s_fac[h],      gp[16 + idx],
                  s_fac[8 + h]  * gp[528 + 16 + idx]);
        float b = fmaf(s_fac[16 + h], gp[1056 + 16 + idx],
                  s_fac[24 + h] * gp[1584 + 16 + idx]);
        s_T[idx] = a + b;
    }
    __syncthreads();

    // node_features -> smem
    {
        int hv = tid, h = hv >> 5;
        const float* st = s_T + h * 64;
        float a0 = g_VnT[(size_t)i * 256 + hv] * maski;
        float a1 = 0.f;
        #pragma unroll 8
        for (int e = 0; e < 64; e += 2) {
            a0 = fmaf(g_WveT[e * 256 + hv],       st[e],     a0);
            a1 = fmaf(g_WveT[(e + 1) * 256 + hv], st[e + 1], a1);
        }
        s_nf[hv] = a0 + a1;
    }
    __syncthreads();

    // fused post: r<128 -> node_out[r,i]; r>=128 -> hEo[r-128,i]
    if (tid < 192) {
        int r = tid;
        const float* wt = g_WT + r;
        float a0 = 0.f, a1 = 0.f;
        #pragma unroll 8
        for (int k = 0; k < 256; k += 2) {
            a0 = fmaf(wt[k * 192],       s_nf[k],     a0);
            a1 = fmaf(wt[(k + 1) * 192], s_nf[k + 1], a1);
        }
        float acc = a0 + a1;
        if (r < 128) out[r * N + i] = acc;
        else         g_hEo[(r - 128) * N + i] = 0.5f * acc;
    }
}

// ============================================================
// Kernel 4: edge_out (R13-proven). grid(576), 256 thr, 2 CTAs/SM.
// CTA tile 64o x 256c, thread 8o x 8c, FFMA2 o-pairs, cp.async.
// ============================================================
#define EG_ST 260
#define EDGE_SMEM ((64*68 + 64*EG_ST) * 4)

__global__ __launch_bounds__(256, 2) void k_edge(
    const float* __restrict__ edges,
    const float* __restrict__ We,
    float* __restrict__ out)
{
    extern __shared__ float esm[];
    float* Ws = esm;              // [64][68]  Ws[e][o]
    float* Es = esm + 64 * 68;    // [64][260]

    int tid = threadIdx.x, lane = tid & 31, wid = tid >> 5;
    size_t cbase = (size_t)blockIdx.x * 256;

    #pragma unroll
    for (int it = 0; it < 8; it++) {
        int idx = it * 256 + tid;
        int e = idx >> 6, c4 = idx & 63;
        cp16(&Es[e * EG_ST + c4 * 4], edges + (size_t)e * NN + cbase + c4 * 4);
    }
    CP_COMMIT();
    #pragma unroll
    for (int it = 8; it < 16; it++) {
        int idx = it * 256 + tid;
        int e = idx >> 6, c4 = idx & 63;
        cp16(&Es[e * EG_ST + c4 * 4], edges + (size_t)e * NN + cbase + c4 * 4);
    }
    CP_COMMIT();

    {
        int o = tid >> 2, e0 = (tid & 3) * 16;
        const float* wp = We + o * 320 + 256 + e0;
        #pragma unroll
        for (int u = 0; u < 16; u += 4) {
            float4 w = *(const float4*)(wp + u);
            Ws[(e0+u+0)*68 + o] = w.x; Ws[(e0+u+1)*68 + o] = w.y;
            Ws[(e0+u+2)*68 + o] = w.z; Ws[(e0+u+3)*68 + o] = w.w;
        }
    }

    int o0 = wid * 8;
    int cl = lane * 4;

    unsigned long long acc2[4][8];
    #pragma unroll
    for (int op = 0; op < 4; op++)
        #pragma unroll
        for (int p = 0; p < 8; p++) acc2[op][p] = 0ull;

    CP_WAIT(1);
    __syncthreads();
    #pragma unroll 4
    for (int e = 0; e < 32; e++) {
        const float* wr = Ws + e * 68 + o0;
        F4U w0; w0.f = *(const float4*)wr;
        F4U w1; w1.f = *(const float4*)(wr + 4);
        unsigned long long wd[4] = { w0.u[0], w0.u[1], w1.u[0], w1.u[1] };
        const float* er = Es + e * EG_ST + cl;
        float4 ea = *(const float4*)er;
        float4 eb = *(const float4*)(er + 128);
        float ev[8] = { ea.x, ea.y, ea.z, ea.w, eb.x, eb.y, eb.z, eb.w };
        #pragma unroll
        for (int p = 0; p < 8; p++) {
            unsigned long long evd = pk2(ev[p], ev[p]);
            acc2[0][p] = fma2(wd[0], evd, acc2[0][p]);
            acc2[1][p] = fma2(wd[1], evd, acc2[1][p]);
            acc2[2][p] = fma2(wd[2], evd, acc2[2][p]);
            acc2[3][p] = fma2(wd[3], evd, acc2[3][p]);
        }
    }
    CP_WAIT(0);
    __syncthreads();
    #pragma unroll 4
    for (int e = 32; e < 64; e++) {
        const float* wr = Ws + e * 68 + o0;
        F4U w0; w0.f = *(const float4*)wr;
        F4U w1; w1.f = *(const float4*)(wr + 4);
        unsigned long long wd[4] = { w0.u[0], w0.u[1], w1.u[0], w1.u[1] };
        const float* er = Es + e * EG_ST + cl;
        float4 ea = *(const float4*)er;
        float4 eb = *(const float4*)(er + 128);
        float ev[8] = { ea.x, ea.y, ea.z, ea.w, eb.x, eb.y, eb.z, eb.w };
        #pragma unroll
        for (int p = 0; p < 8; p++) {
            unsigned long long evd = pk2(ev[p], ev[p]);
            acc2[0][p] = fma2(wd[0], evd, acc2[0][p]);
            acc2[1][p] = fma2(wd[1], evd, acc2[1][p]);
            acc2[2][p] = fma2(wd[2], evd, acc2[2][p]);
            acc2[3][p] = fma2(wd[3], evd, acc2[3][p]);
        }
    }

    float* ob = out + 128 * N;
    #pragma unroll
    for (int s = 0; s < 2; s++) {
        size_t c = cbase + cl + s * 128;
        int ii = (int)(c / 384), jj = (int)(c % 384);
        #pragma unroll
        for (int op = 0; op < 4; op++) {
            int oA = o0 + 2 * op, oB = oA + 1;
            float eoiA = g_hEo[oA * N + ii];
            float eoiB = g_hEo[oB * N + ii];
            float4 ejA = *(const float4*)(g_hEo + oA * N + jj);
            float4 ejB = *(const float4*)(g_hEo + oB * N + jj);
            float2 v0 = upk(acc2[op][s*4+0]);
            float2 v1 = upk(acc2[op][s*4+1]);
            float2 v2 = upk(acc2[op][s*4+2]);
            float2 v3 = upk(acc2[op][s*4+3]);
            float* pA = ob + (size_t)oA * NN + c;
            float* pB = ob + (size_t)oB * NN + c;
            *(float4*)pA = make_float4(v0.x + eoiA + ejA.x, v1.x + eoiA + ejA.y,
                                       v2.x + eoiA + ejA.z, v3.x + eoiA + ejA.w);
            *(float4*)pB = make_float4(v0.y + eoiB + ejB.x, v1.y + eoiB + ejB.y,
                                       v2.y + eoiB + ejB.z, v3.y + eoiB + ejB.w);
        }
    }
}

// ============================================================
extern "C" void kernel_launch(void* const* d_in, const int* in_sizes, int n_in,
                              void* d_out, int out_size)
{
    const float* nodes = (const float*)d_in[0];
    const float* edges = (const float*)d_in[1];
    const unsigned int* mask = (const unsigned int*)d_in[2];
    const float* Wq = (const float*)d_in[3];
    const float* Wk = (const float*)d_in[4];
    const float* Wv = (const float*)d_in[5];
    const float* Wo = (const float*)d_in[6];
    const float* We = (const float*)d_in[7];
    float* out = (float*)d_out;

    cudaFuncSetAttribute(k_edge, cudaFuncAttributeMaxDynamicSharedMemorySize, EDGE_SMEM);

    k_prep<<<dim3(25, 12), 256>>>(nodes, Wq, Wk, Wv, Wo, We, mask);  // #1
    k_attnA<<<1536, 256>>>(edges);                                   // #2
    k_attnB<<<384, 256>>>(out);                                      // #3
    k_edge<<<576, 256, EDGE_SMEM>>>(edges, We, out);                 // #4
}